// round 5
// baseline (speedup 1.0000x reference)
#include <cuda_runtime.h>
#include <cstdint>

#define KST   48
#define TLEN  512
#define TILE  8               // steps per emission tile (= renorm cadence)
#define NTILE 64

// ---- packed f32x2 helpers (sm_100+) ----
__device__ __forceinline__ unsigned long long fma2(unsigned long long a,
                                                   unsigned long long b,
                                                   unsigned long long c) {
    unsigned long long d;
    asm("fma.rn.f32x2 %0, %1, %2, %3;" : "=l"(d) : "l"(a), "l"(b), "l"(c));
    return d;
}
__device__ __forceinline__ unsigned long long add2(unsigned long long a,
                                                   unsigned long long b) {
    unsigned long long d;
    asm("add.rn.f32x2 %0, %1, %2;" : "=l"(d) : "l"(a), "l"(b));
    return d;
}
__device__ __forceinline__ unsigned long long pack2(float lo, float hi) {
    unsigned long long r;
    asm("mov.b64 %0, {%1, %2};" : "=l"(r) : "f"(lo), "f"(hi));
    return r;
}
__device__ __forceinline__ float2 unpack2(unsigned long long v) {
    float2 f;
    asm("mov.b64 {%0, %1}, %2;" : "=f"(f.x), "=f"(f.y) : "l"(v));
    return f;
}
__device__ __forceinline__ float ex2f(float x) {
    float y; asm("ex2.approx.f32 %0, %1;" : "=f"(y) : "f"(x)); return y;
}
__device__ __forceinline__ float lg2f(float x) {
    float y; asm("lg2.approx.f32 %0, %1;" : "=f"(y) : "f"(x)); return y;
}

__global__ __launch_bounds__(32)
void crf_nll_kernel(const float* __restrict__ emis,   // [B, T, K]
                    const int*   __restrict__ lab,    // [B, T]
                    const float* __restrict__ trans,  // [K, K]
                    float*       __restrict__ out)    // [B]
{
    __shared__ __align__(16) float etile[TILE * KST + 16]; // emission tile (log2 units)
    __shared__ __align__(16) float pbuf[KST];              // p = 2^alpha broadcast

    const int l = threadIdx.x;          // lane; owns states c0=l and c1=l+32 (pad if >=48)
    const int b = blockIdx.x;
    const int c1 = l + 32;
    const bool real1 = (c1 < KST);
    const float LOG2E = 1.4426950408889634f;
    const float LN2   = 0.6931471805599453f;
    const float NEG_INF = __int_as_float(0xff800000);

    const float* eb = emis + (size_t)b * TLEN * KST;
    const int*   lb = lab  + b * TLEN;

    // E columns in registers, packed pairs over rows (linear domain); pad col -> 0
    unsigned long long ec2a[KST / 2], ec2b[KST / 2];
    const int cc1 = real1 ? c1 : 0;
#pragma unroll
    for (int q = 0; q < KST / 2; ++q) {
        float a0 = __expf(trans[(2 * q)     * KST + l]);
        float a1 = __expf(trans[(2 * q + 1) * KST + l]);
        ec2a[q] = pack2(a0, a1);
        float b0 = real1 ? __expf(trans[(2 * q)     * KST + cc1]) : 0.f;
        float b1 = real1 ? __expf(trans[(2 * q + 1) * KST + cc1]) : 0.f;
        ec2b[q] = pack2(b0, b1);
    }

    // ---- sequence score (unary + binary), strided across 32 lanes ----
    float part = 0.f;
    for (int t = l; t < TLEN; t += 32) {
        int l0 = lb[t];
        part += eb[t * KST + l0];
        if (t + 1 < TLEN) part += trans[l0 * KST + lb[t + 1]];
    }
#pragma unroll
    for (int d = 16; d >= 1; d >>= 1)
        part += __shfl_xor_sync(0xffffffffu, part, d);
    const float score = part;

    // ---- forward recursion, log2 domain ----
    float a0 = eb[l] * LOG2E;
    float a1 = real1 ? eb[c1] * LOG2E : NEG_INF;
    float M  = 0.f;

    // prefetch tile 0 (t = 1..8): 96 float4, 3 per lane
    const float4* src4  = (const float4*)eb;
    const int     maxf4 = (TLEN * KST) / 4 - 1;
    float4 r0 = src4[12 + l], r1 = src4[44 + l], r2 = src4[76 + l];

    for (int gt = 0; gt < NTILE; ++gt) {
        // renormalize: warp max (pad alphas are -inf, ignored by max)
        float m = fmaxf(a0, a1);
#pragma unroll
        for (int d = 16; d >= 1; d >>= 1)
            m = fmaxf(m, __shfl_xor_sync(0xffffffffu, m, d));
        a0 -= m; a1 -= m; M += m;

        // commit current tile (scaled to log2 units)
        float4 w;
        w = r0; w.x *= LOG2E; w.y *= LOG2E; w.z *= LOG2E; w.w *= LOG2E;
        ((float4*)etile)[l]      = w;
        w = r1; w.x *= LOG2E; w.y *= LOG2E; w.z *= LOG2E; w.w *= LOG2E;
        ((float4*)etile)[32 + l] = w;
        w = r2; w.x *= LOG2E; w.y *= LOG2E; w.z *= LOG2E; w.w *= LOG2E;
        ((float4*)etile)[64 + l] = w;

        // prefetch next tile (clamped tail rows never consumed)
        if (gt + 1 < NTILE) {
            int base = (1 + TILE * (gt + 1)) * (KST / 4);
            r0 = src4[min(base + l,      maxf4)];
            r1 = src4[min(base + 32 + l, maxf4)];
            r2 = src4[min(base + 64 + l, maxf4)];
        }
        __syncwarp();

#pragma unroll
        for (int tt = 0; tt < TILE; ++tt) {
            const int t = 1 + TILE * gt + tt;
            if (t >= TLEN) break;                 // uniform

            float p0 = ex2f(a0), p1 = ex2f(a1);   // pad: ex2(-inf) = +0
            pbuf[l] = p0;
            if (l < 16) pbuf[c1] = p1;
            __syncwarp();

            float e0 = etile[tt * KST + l];
            float e1 = etile[tt * KST + (real1 ? c1 : l)];   // pad value unused

            const ulonglong2* pp = (const ulonglong2*)pbuf;
            unsigned long long c00 = 0, c01 = 0, c10 = 0, c11 = 0;
#pragma unroll
            for (int q = 0; q < KST / 4; ++q) {   // 12 x LDS.128 (broadcast)
                ulonglong2 v = pp[q];
                c00 = fma2(v.x, ec2a[2 * q],     c00);
                c01 = fma2(v.y, ec2a[2 * q + 1], c01);
                c10 = fma2(v.x, ec2b[2 * q],     c10);
                c11 = fma2(v.y, ec2b[2 * q + 1], c11);
            }
            c00 = add2(c00, c01);
            c10 = add2(c10, c11);
            float2 f0 = unpack2(c00), f1 = unpack2(c10);

            a0 = lg2f(f0.x + f0.y) + e0;
            a1 = lg2f(f1.x + f1.y) + e1;          // pad: lg2(0) = -inf
            __syncwarp();                          // order reads before next step's STS
        }
    }

    // ---- final logsumexp (log2 domain) + output ----
    float m = fmaxf(a0, a1);
#pragma unroll
    for (int d = 16; d >= 1; d >>= 1)
        m = fmaxf(m, __shfl_xor_sync(0xffffffffu, m, d));
    float ssum = ex2f(a0 - m) + ex2f(a1 - m);     // pad contributes 0
#pragma unroll
    for (int d = 16; d >= 1; d >>= 1)
        ssum += __shfl_xor_sync(0xffffffffu, ssum, d);

    if (l == 0)
        out[b] = LN2 * (lg2f(ssum) + m + M) - score;
}

extern "C" void kernel_launch(void* const* d_in, const int* in_sizes, int n_in,
                              void* d_out, int out_size)
{
    const float* emis  = (const float*)d_in[0];   // output (B,T,K) fp32
    const int*   lab   = (const int*)  d_in[1];   // label_input (B,T) int32
    const float* trans = (const float*)d_in[2];   // transition_params (K,K) fp32
    float*       outp  = (float*)d_out;           // (B,) fp32

    const int B = out_size;                       // 1024
    crf_nll_kernel<<<B, 32>>>(emis, lab, trans, outp);
}

// round 7
// speedup vs baseline: 1.0515x; 1.0515x over previous
#include <cuda_runtime.h>
#include <cstdint>

#define KST   48
#define TLEN  512
#define GRP   16              // lanes per batch
#define NB    4               // batches per block
#define BDIM  (GRP * NB)      // 64 threads = 2 independent warps
#define TILE  8               // steps per tile (= renorm cadence)
#define ETS   400             // etile per-batch float stride

// ---- packed f32x2 helpers (sm_100+) ----
__device__ __forceinline__ unsigned long long fma2(unsigned long long a,
                                                   unsigned long long b,
                                                   unsigned long long c) {
    unsigned long long d;
    asm("fma.rn.f32x2 %0, %1, %2, %3;" : "=l"(d) : "l"(a), "l"(b), "l"(c));
    return d;
}
__device__ __forceinline__ unsigned long long add2(unsigned long long a,
                                                   unsigned long long b) {
    unsigned long long d;
    asm("add.rn.f32x2 %0, %1, %2;" : "=l"(d) : "l"(a), "l"(b));
    return d;
}
__device__ __forceinline__ unsigned long long pack2(float lo, float hi) {
    unsigned long long r;
    asm("mov.b64 %0, {%1, %2};" : "=l"(r) : "f"(lo), "f"(hi));
    return r;
}
__device__ __forceinline__ float2 unpack2(unsigned long long v) {
    float2 f;
    asm("mov.b64 {%0, %1}, %2;" : "=f"(f.x), "=f"(f.y) : "l"(v));
    return f;
}
__device__ __forceinline__ float ex2f(float x) {
    float y; asm("ex2.approx.f32 %0, %1;" : "=f"(y) : "f"(x)); return y;
}
__device__ __forceinline__ float lg2f(float x) {
    float y; asm("lg2.approx.f32 %0, %1;" : "=f"(y) : "f"(x)); return y;
}

#define LOG2E 1.4426950408889634f
#define LN2   0.6931471805599453f

// one recursion step; PAR is a compile-time literal (branch-free body)
#define STEP(TT, PAR)                                                          \
{                                                                              \
    float p0 = ex2f(a0), p1 = ex2f(a1), p2 = ex2f(a2);                         \
    float* pb = &pbuf[PAR][0][0] + g * KST;                                    \
    pb[l] = p0; pb[l + 16] = p1; pb[l + 32] = p2;                              \
    float e0 = myTile[(TT) * KST + l];                                         \
    float e1 = myTile[(TT) * KST + l + 16];                                    \
    float e2 = myTile[(TT) * KST + l + 32];                                    \
    __syncwarp();                                                              \
    const ulonglong2* pp = (const ulonglong2*)pb;                              \
    unsigned long long cA[3] = {0,0,0}, cB[3] = {0,0,0}, cC[3] = {0,0,0};      \
    _Pragma("unroll")                                                          \
    for (int c = 0; c < 3; ++c) {                                              \
        _Pragma("unroll")                                                      \
        for (int k = 0; k < 4; ++k) {                                          \
            ulonglong2 v = pp[4 * c + k];                                      \
            int m = 8 * c + 2 * k;                                             \
            cA[c] = fma2(v.x, ecA[m],     cA[c]);                              \
            cA[c] = fma2(v.y, ecA[m + 1], cA[c]);                              \
            cB[c] = fma2(v.x, ecB[m],     cB[c]);                              \
            cB[c] = fma2(v.y, ecB[m + 1], cB[c]);                              \
            cC[c] = fma2(v.x, ecC[m],     cC[c]);                              \
            cC[c] = fma2(v.y, ecC[m + 1], cC[c]);                              \
        }                                                                      \
    }                                                                          \
    float2 fA = unpack2(add2(cA[0], add2(cA[1], cA[2])));                      \
    float2 fB = unpack2(add2(cB[0], add2(cB[1], cB[2])));                      \
    float2 fC = unpack2(add2(cC[0], add2(cC[1], cC[2])));                      \
    a0 = fmaf(e0, LOG2E, lg2f(fA.x + fA.y));                                   \
    a1 = fmaf(e1, LOG2E, lg2f(fB.x + fB.y));                                   \
    a2 = fmaf(e2, LOG2E, lg2f(fC.x + fC.y));                                   \
}

#define RENORM()                                                               \
{                                                                              \
    float m = fmaxf(a0, fmaxf(a1, a2));                                        \
    _Pragma("unroll")                                                          \
    for (int d = 8; d >= 1; d >>= 1)                                           \
        m = fmaxf(m, __shfl_xor_sync(0xffffffffu, m, d, 16));                  \
    a0 -= m; a1 -= m; a2 -= m; M += m;                                         \
}

#define COMMIT()                                                               \
{                                                                              \
    _Pragma("unroll")                                                          \
    for (int k = 0; k < 6; ++k)                                                \
        ((float4*)myTile)[l + 16 * k] = r[k];                                  \
}

__global__ __launch_bounds__(BDIM)
void crf_nll_kernel(const float* __restrict__ emis,   // [B, T, K]
                    const int*   __restrict__ lab,    // [B, T]
                    const float* __restrict__ trans,  // [K, K]
                    float*       __restrict__ out)    // [B]
{
    __shared__ __align__(16) float etile[NB * ETS];      // raw emission tiles
    __shared__ __align__(16) float pbuf[2][NB][KST];     // ping-pong p = 2^alpha

    const int tid = threadIdx.x;
    const int g   = tid >> 4;          // batch within block
    const int l   = tid & 15;          // lane within batch group
    const int b   = blockIdx.x * NB + g;

    const float* eb = emis + (size_t)b * TLEN * KST;
    const int*   lb = lab  + b * TLEN;

    // E columns for states l, l+16, l+32 as 24 packed f32x2 each (pairs over i)
    unsigned long long ecA[KST / 2], ecB[KST / 2], ecC[KST / 2];
#pragma unroll
    for (int q = 0; q < KST / 2; ++q) {
        const float* t0 = trans + (2 * q) * KST;
        const float* t1 = trans + (2 * q + 1) * KST;
        ecA[q] = pack2(__expf(t0[l]),      __expf(t1[l]));
        ecB[q] = pack2(__expf(t0[l + 16]), __expf(t1[l + 16]));
        ecC[q] = pack2(__expf(t0[l + 32]), __expf(t1[l + 32]));
    }

    // ---- sequence score (unary + binary), strided over 16 lanes ----
    float part = 0.f;
    for (int t = l; t < TLEN; t += GRP) {
        int l0 = lb[t];
        part += eb[t * KST + l0];
        if (t + 1 < TLEN) part += trans[l0 * KST + lb[t + 1]];
    }
#pragma unroll
    for (int d = 8; d >= 1; d >>= 1)
        part += __shfl_xor_sync(0xffffffffu, part, d, 16);
    const float score = part;

    // ---- forward recursion (log2 domain) ----
    float a0 = eb[l]      * LOG2E;
    float a1 = eb[l + 16] * LOG2E;
    float a2 = eb[l + 32] * LOG2E;
    float M  = 0.f;

    const float4* src4  = (const float4*)eb;
    const int     maxf4 = (TLEN * KST) / 4 - 1;
    float*        myTile = etile + g * ETS;

    // prefetch tile 0 (t = 1..8): 96 float4 per batch, 6 per lane
    float4 r[6];
#pragma unroll
    for (int k = 0; k < 6; ++k)
        r[k] = src4[12 + l + 16 * k];

    for (int gt = 0; gt < 63; ++gt) {            // 63 full tiles
        RENORM();
        COMMIT();
        {   // prefetch tile gt+1 (clamped; clamped rows only hit in tail pad)
            int base = (9 + TILE * gt) * (KST / 4);
#pragma unroll
            for (int k = 0; k < 6; ++k)
                r[k] = src4[min(base + l + 16 * k, maxf4)];
        }
        __syncwarp();                            // commit visible before e-reads

        STEP(0, 0) STEP(1, 1) STEP(2, 0) STEP(3, 1)
        STEP(4, 0) STEP(5, 1) STEP(6, 0) STEP(7, 1)
    }

    // tail tile: t = 505..511 (7 steps)
    RENORM();
    COMMIT();
    __syncwarp();
    STEP(0, 0) STEP(1, 1) STEP(2, 0) STEP(3, 1)
    STEP(4, 0) STEP(5, 1) STEP(6, 0)

    // ---- final logsumexp + output ----
    float m = fmaxf(a0, fmaxf(a1, a2));
#pragma unroll
    for (int d = 8; d >= 1; d >>= 1)
        m = fmaxf(m, __shfl_xor_sync(0xffffffffu, m, d, 16));
    float ssum = ex2f(a0 - m) + ex2f(a1 - m) + ex2f(a2 - m);
#pragma unroll
    for (int d = 8; d >= 1; d >>= 1)
        ssum += __shfl_xor_sync(0xffffffffu, ssum, d, 16);

    if (l == 0)
        out[b] = LN2 * (lg2f(ssum) + m + M) - score;
}

extern "C" void kernel_launch(void* const* d_in, const int* in_sizes, int n_in,
                              void* d_out, int out_size)
{
    const float* emis  = (const float*)d_in[0];   // output (B,T,K) fp32
    const int*   lab   = (const int*)  d_in[1];   // label_input (B,T) int32
    const float* trans = (const float*)d_in[2];   // transition_params (K,K) fp32
    float*       outp  = (float*)d_out;           // (B,) fp32

    const int B = out_size;                       // 1024
    crf_nll_kernel<<<B / NB, BDIM>>>(emis, lab, trans, outp);
}

// round 10
// speedup vs baseline: 1.4210x; 1.3514x over previous
#include <cuda_runtime.h>
#include <cstdint>

#define KST   48
#define TLEN  512
#define GRP   16              // lanes per batch
#define NB    2               // batches per block (one warp)
#define BDIM  32
#define TILE  8               // steps per tile (= renorm cadence)
#define ETS   400             // etile per-batch float stride (bank offset 16)

// ---- packed f32x2 helpers (sm_100+) ----
__device__ __forceinline__ unsigned long long fma2(unsigned long long a,
                                                   unsigned long long b,
                                                   unsigned long long c) {
    unsigned long long d;
    asm("fma.rn.f32x2 %0, %1, %2, %3;" : "=l"(d) : "l"(a), "l"(b), "l"(c));
    return d;
}
__device__ __forceinline__ unsigned long long add2(unsigned long long a,
                                                   unsigned long long b) {
    unsigned long long d;
    asm("add.rn.f32x2 %0, %1, %2;" : "=l"(d) : "l"(a), "l"(b));
    return d;
}
__device__ __forceinline__ unsigned long long pack2(float lo, float hi) {
    unsigned long long r;
    asm("mov.b64 %0, {%1, %2};" : "=l"(r) : "f"(lo), "f"(hi));
    return r;
}
__device__ __forceinline__ float2 unpack2(unsigned long long v) {
    float2 f;
    asm("mov.b64 {%0, %1}, %2;" : "=f"(f.x), "=f"(f.y) : "l"(v));
    return f;
}
__device__ __forceinline__ float ex2f(float x) {
    float y; asm("ex2.approx.f32 %0, %1;" : "=f"(y) : "f"(x)); return y;
}
__device__ __forceinline__ float lg2f(float x) {
    float y; asm("lg2.approx.f32 %0, %1;" : "=f"(y) : "f"(x)); return y;
}

#define LOG2E 1.4426950408889634f
#define LN2   0.6931471805599453f

__global__ __launch_bounds__(BDIM)
void crf_nll_kernel(const float* __restrict__ emis,   // [B, T, K]
                    const int*   __restrict__ lab,    // [B, T]
                    const float* __restrict__ trans,  // [K, K]
                    float*       __restrict__ out)    // [B]
{
    __shared__ __align__(16) float etile[NB * ETS];      // EXP'd emission weights
    __shared__ __align__(16) float pbuf[2][NB][KST];     // ping-pong p (linear domain)

    const int tid = threadIdx.x;
    const int g   = tid >> 4;          // batch within block (0/1)
    const int l   = tid & 15;          // lane within batch group
    const int b   = blockIdx.x * NB + g;

    const float* eb = emis + (size_t)b * TLEN * KST;
    const int*   lb = lab  + b * TLEN;

    // E columns for states l, l+16, l+32 as 24 packed f32x2 each (pairs over i)
    unsigned long long ecA[KST / 2], ecB[KST / 2], ecC[KST / 2];
#pragma unroll
    for (int q = 0; q < KST / 2; ++q) {
        const float* t0 = trans + (2 * q) * KST;
        const float* t1 = trans + (2 * q + 1) * KST;
        ecA[q] = pack2(__expf(t0[l]),      __expf(t1[l]));
        ecB[q] = pack2(__expf(t0[l + 16]), __expf(t1[l + 16]));
        ecC[q] = pack2(__expf(t0[l + 32]), __expf(t1[l + 32]));
    }

    // ---- sequence score (unary + binary), strided over 16 lanes ----
    float part = 0.f;
    for (int t = l; t < TLEN; t += GRP) {
        int l0 = lb[t];
        part += eb[t * KST + l0];
        if (t + 1 < TLEN) part += trans[l0 * KST + lb[t + 1]];
    }
#pragma unroll
    for (int d = 8; d >= 1; d >>= 1)
        part += __shfl_xor_sync(0xffffffffu, part, d, 16);
    const float score = part;

    // ---- forward recursion, LINEAR domain with exact pow2 renorm ----
    float p0 = ex2f(eb[l]      * LOG2E);
    float p1 = ex2f(eb[l + 16] * LOG2E);
    float p2 = ex2f(eb[l + 32] * LOG2E);
    float M  = 0.f;                      // accumulated log2 scale (integer-valued)

    const float4* src4  = (const float4*)eb;
    const int     maxf4 = (TLEN * KST) / 4 - 1;
    float*        myTile = etile + g * ETS;
    float*        pb0 = &pbuf[0][g][0];
    float*        pb1 = &pbuf[1][g][0];

    // prefetch tile 0 (t = 1..8): 96 float4 per batch, 6 per lane
    float4 r[6];
#pragma unroll
    for (int k = 0; k < 6; ++k)
        r[k] = src4[12 + l + 16 * k];

    int par = 0;
    for (int gt = 0; gt < 64; ++gt) {
        // renormalize: exact power-of-2 scale so p stays in range
        float m = fmaxf(p0, fmaxf(p1, p2));
#pragma unroll
        for (int d = 8; d >= 1; d >>= 1)
            m = fmaxf(m, __shfl_xor_sync(0xffffffffu, m, d, 16));
        float kk = ceilf(lg2f(m));
        float sc = ex2f(-kk);            // exact pow2: error-free rescale
        p0 *= sc; p1 *= sc; p2 *= sc;
        M  += kk;

        // commit current tile as EXP'd weights: w = 2^(e * log2e) = exp(e)
#pragma unroll
        for (int k = 0; k < 6; ++k) {
            float4 v = r[k];
            v.x = ex2f(v.x * LOG2E);
            v.y = ex2f(v.y * LOG2E);
            v.z = ex2f(v.z * LOG2E);
            v.w = ex2f(v.w * LOG2E);
            ((float4*)myTile)[l + 16 * k] = v;
        }

        // prefetch next tile (clamped rows only hit in unused tail pad)
        if (gt + 1 < 64) {
            int base = (9 + TILE * gt) * (KST / 4);
#pragma unroll
            for (int k = 0; k < 6; ++k)
                r[k] = src4[min(base + l + 16 * k, maxf4)];
        }
        __syncwarp();

#pragma unroll
        for (int tt = 0; tt < TILE; ++tt) {
            const int t = 1 + TILE * gt + tt;
            if (t >= TLEN) break;                 // uniform

            float* pb = par ? pb1 : pb0;
            pb[l] = p0; pb[l + 16] = p1; pb[l + 32] = p2;
            __syncwarp();

            // pre-exponentiated weights: plain LDS, no MUFU on the chain
            float w0 = myTile[tt * KST + l];
            float w1 = myTile[tt * KST + l + 16];
            float w2 = myTile[tt * KST + l + 32];

            // 4 chains of depth 6 per output (shorter serial fma tail)
            const ulonglong2* pp = (const ulonglong2*)pb;
            unsigned long long cA[4] = {0,0,0,0}, cB[4] = {0,0,0,0}, cC[4] = {0,0,0,0};
#pragma unroll
            for (int q = 0; q < KST / 4; ++q) {   // 12 x LDS.128 broadcast
                ulonglong2 v = pp[q];
                const int h0 = (2 * q)     & 3;
                const int h1 = (2 * q + 1) & 3;
                cA[h0] = fma2(v.x, ecA[2 * q],     cA[h0]);
                cA[h1] = fma2(v.y, ecA[2 * q + 1], cA[h1]);
                cB[h0] = fma2(v.x, ecB[2 * q],     cB[h0]);
                cB[h1] = fma2(v.y, ecB[2 * q + 1], cB[h1]);
                cC[h0] = fma2(v.x, ecC[2 * q],     cC[h0]);
                cC[h1] = fma2(v.y, ecC[2 * q + 1], cC[h1]);
            }
            float2 f0 = unpack2(add2(add2(cA[0], cA[1]), add2(cA[2], cA[3])));
            float2 f1 = unpack2(add2(add2(cB[0], cB[1]), add2(cB[2], cB[3])));
            float2 f2 = unpack2(add2(add2(cC[0], cC[1]), add2(cC[2], cC[3])));

            p0 = (f0.x + f0.y) * w0;              // no log/exp on the chain
            p1 = (f1.x + f1.y) * w1;
            p2 = (f2.x + f2.y) * w2;
            par ^= 1;
        }
    }

    // ---- final: log_norm = ln(sum p) + ln2 * M ----
    float ssum = p0 + p1 + p2;
#pragma unroll
    for (int d = 8; d >= 1; d >>= 1)
        ssum += __shfl_xor_sync(0xffffffffu, ssum, d, 16);

    if (l == 0)
        out[b] = LN2 * (lg2f(ssum) + M) - score;
}

extern "C" void kernel_launch(void* const* d_in, const int* in_sizes, int n_in,
                              void* d_out, int out_size)
{
    const float* emis  = (const float*)d_in[0];   // output (B,T,K) fp32
    const int*   lab   = (const int*)  d_in[1];   // label_input (B,T) int32
    const float* trans = (const float*)d_in[2];   // transition_params (K,K) fp32
    float*       outp  = (float*)d_out;           // (B,) fp32

    const int B = out_size;                       // 1024
    crf_nll_kernel<<<B / NB, BDIM>>>(emis, lab, trans, outp);
}